// round 12
// baseline (speedup 1.0000x reference)
#include <cuda_runtime.h>
#include <cstdint>

// Fixed shapes: I(16,3,512,512), T(16,256), P(3,16), Q(16,3)
#define BS        16
#define CHANS     3
#define HW        (512 * 512)          // 262144 floats per channel
#define NCH       (BS * CHANS)         // 48 channels
#define PARTS     32                   // partials per channel
#define NBLOCKS   (NCH * PARTS)        // 1536 blocks
#define RFLOATS   8192                 // floats per block (32KB)
#define RBYTES    (RFLOATS * 4)
#define THREADS   256
#define KDIM      16

// Deterministic scratch: fixed write slots, no atomics.
__device__ float g_partials[NBLOCKS];

__device__ __forceinline__ uint32_t smem_u32(const void* p) {
    uint32_t a;
    asm("{ .reg .u64 x; cvta.to.shared.u64 x, %1; cvt.u32.u64 %0, x; }"
        : "=r"(a) : "l"(p));
    return a;
}

__global__ __launch_bounds__(THREADS)
void dncm_reduce_kernel(const float* __restrict__ I) {
    __shared__ __align__(128) float buf[RFLOATS];        // 32KB TMA landing pad
    __shared__ __align__(8)  unsigned long long mbar;

    const int bid = blockIdx.x;          // 0 .. 1535
    const int t   = threadIdx.x;
    const uint32_t mb = smem_u32(&mbar);

    // --- init mbarrier, then issue one 32KB bulk copy from a single thread ---
    if (t == 0) {
        asm volatile("mbarrier.init.shared.b64 [%0], 1;" :: "r"(mb) : "memory");
        asm volatile("fence.mbarrier_init.release.cluster;" ::: "memory");
    }
    __syncthreads();

    if (t == 0) {
        asm volatile("mbarrier.arrive.expect_tx.shared.b64 _, [%0], %1;"
                     :: "r"(mb), "r"((uint32_t)RBYTES) : "memory");
        const float* src = I + (size_t)bid * RFLOATS;
        asm volatile("cp.async.bulk.shared::cluster.global.mbarrier::complete_tx::bytes "
                     "[%0], [%1], %2, [%3];"
                     :: "r"(smem_u32(buf)), "l"(src), "r"((uint32_t)RBYTES), "r"(mb)
                     : "memory");
    }

    // --- all threads wait for the TMA completion (phase 0) ---
    {
        uint32_t done;
        asm volatile("{\n\t.reg .pred p;\n\t"
                     "mbarrier.try_wait.parity.acquire.cta.shared::cta.b64 p, [%1], 0;\n\t"
                     "selp.b32 %0, 1, 0, p;\n\t}"
                     : "=r"(done) : "r"(mb) : "memory");
        while (!done) {
            asm volatile("{\n\t.reg .pred p;\n\t"
                         "mbarrier.try_wait.parity.acquire.cta.shared::cta.b64 p, [%1], 0, 0x989680;\n\t"
                         "selp.b32 %0, 1, 0, p;\n\t}"
                         : "=r"(done) : "r"(mb) : "memory");
        }
    }

    // --- sum 8192 floats from SMEM: 8 float4 per thread, conflict-free stride ---
    const float4* __restrict__ b4 = reinterpret_cast<const float4*>(buf);
    float s = 0.0f;
    #pragma unroll
    for (int i = 0; i < 8; i++) {
        float4 v = b4[t + i * THREADS];
        s += (v.x + v.y) + (v.z + v.w);
    }

    #pragma unroll
    for (int off = 16; off > 0; off >>= 1)
        s += __shfl_xor_sync(0xffffffffu, s, off);

    __shared__ float wsum[THREADS / 32];
    if ((t & 31) == 0) wsum[t >> 5] = s;
    __syncthreads();

    if (t == 0) {
        float tot = 0.0f;
        #pragma unroll
        for (int i = 0; i < THREADS / 32; i++) tot += wsum[i];
        g_partials[bid] = tot;   // fixed slot -> deterministic
        cudaTriggerProgrammaticLaunchCompletion();
    }
}

// Epilogue (PDL secondary): prefetch T/Q/P before gridDepSync, then consume
// 1536 partials. 768 threads = 48 teams x 16 lanes, 2 loads per lane.
__global__ __launch_bounds__(768)
void dncm_final_kernel(const float* __restrict__ T,
                       const float* __restrict__ P,
                       const float* __restrict__ Q,
                       float* __restrict__ out) {
    const int t  = threadIdx.x;        // 0..767
    const int ch = t >> 4;             // 0..47
    const int j  = t & 15;             // lane within team

    // ---- Prefetch phase (overlaps with primary tail) ----
    const int b = t >> 4;              // batch (valid for t < 256)
    const int k = t & 15;
    float4 t0, t1, t2, t3;
    float r[KDIM];
    float P0 = 0.f, P1 = 0.f, P2 = 0.f;
    if (t < 256) {
        const float4* __restrict__ Tv =
            reinterpret_cast<const float4*>(T + b * (KDIM * KDIM) + k * KDIM);
        t0 = Tv[0]; t1 = Tv[1]; t2 = Tv[2]; t3 = Tv[3];
        #pragma unroll
        for (int q = 0; q < KDIM; q++)
            r[q] = Q[q * 3 + 0] + Q[q * 3 + 1] + Q[q * 3 + 2];
        P0 = P[0 * KDIM + k];
        P1 = P[1 * KDIM + k];
        P2 = P[2 * KDIM + k];
    }

    cudaGridDependencySynchronize();

    // ---- Reduce partials: 16 lanes per channel, 2 loads each ----
    const float* __restrict__ p = g_partials + ch * PARTS;
    float s = p[j] + p[j + 16];
    #pragma unroll
    for (int off = 8; off > 0; off >>= 1)
        s += __shfl_xor_sync(0xffffffffu, s, off);

    __shared__ float S[NCH];
    if (j == 0) S[ch] = s;
    __syncthreads();

    if (t < 256) {
        // A[b,k] = sum_c S[b,c] * P[c,k]
        const float A = S[b * CHANS + 0] * P0
                      + S[b * CHANS + 1] * P1
                      + S[b * CHANS + 2] * P2;

        // d = T_b[k,:] . r
        float d = t0.x * r[0]  + t0.y * r[1]  + t0.z * r[2]  + t0.w * r[3]
                + t1.x * r[4]  + t1.y * r[5]  + t1.z * r[6]  + t1.w * r[7]
                + t2.x * r[8]  + t2.y * r[9]  + t2.z * r[10] + t2.w * r[11]
                + t3.x * r[12] + t3.y * r[13] + t3.z * r[14] + t3.w * r[15];

        float val = d * A;
        #pragma unroll
        for (int off = 8; off > 0; off >>= 1)
            val += __shfl_xor_sync(0xffffffffu, val, off);

        if (k == 0)
            out[b] = val * (1.0f / (float)(HW * CHANS));
    }
}

extern "C" void kernel_launch(void* const* d_in, const int* in_sizes, int n_in,
                              void* d_out, int out_size) {
    const float* I = (const float*)d_in[0];   // (16,3,512,512)
    const float* T = (const float*)d_in[1];   // (16,256)
    const float* P = (const float*)d_in[2];   // (3,16)
    const float* Q = (const float*)d_in[3];   // (16,3)
    float* out = (float*)d_out;               // (16,1)

    dncm_reduce_kernel<<<NBLOCKS, THREADS>>>(I);

    cudaLaunchConfig_t cfg = {};
    cfg.gridDim  = dim3(1, 1, 1);
    cfg.blockDim = dim3(768, 1, 1);
    cfg.dynamicSmemBytes = 0;
    cfg.stream = 0;
    cudaLaunchAttribute attr[1];
    attr[0].id = cudaLaunchAttributeProgrammaticStreamSerialization;
    attr[0].val.programmaticStreamSerializationAllowed = 1;
    cfg.attrs = attr;
    cfg.numAttrs = 1;
    cudaLaunchKernelEx(&cfg, dncm_final_kernel, T, P, Q, out);
}

// round 13
// speedup vs baseline: 1.0208x; 1.0208x over previous
#include <cuda_runtime.h>
#include <cstdint>

// Fixed shapes: I(16,3,512,512), T(16,256), P(3,16), Q(16,3)
#define BS        16
#define CHANS     3
#define HW        (512 * 512)          // 262144 floats per channel
#define NCH       (BS * CHANS)         // 48 channels
#define PARTS     32                   // partials per channel
#define NBLOCKS   (NCH * PARTS)        // 1536 blocks
#define RFLOATS   8192                 // floats per block (32KB total)
#define HALF      4096                 // floats per half (16KB)
#define HBYTES    (HALF * 4)
#define THREADS   256
#define KDIM      16

// Deterministic scratch: fixed write slots, no atomics.
__device__ float g_partials[NBLOCKS];

__device__ __forceinline__ uint32_t smem_u32(const void* p) {
    uint32_t a;
    asm("{ .reg .u64 x; cvta.to.shared.u64 x, %1; cvt.u32.u64 %0, x; }"
        : "=r"(a) : "l"(p));
    return a;
}

__global__ __launch_bounds__(THREADS)
void dncm_reduce_kernel(const float* __restrict__ I) {
    __shared__ __align__(128) float buf[HALF];           // 16KB TMA landing pad
    __shared__ __align__(8)  unsigned long long mbar;

    const int bid = blockIdx.x;          // 0 .. 1535
    const int t   = threadIdx.x;
    const uint32_t mb = smem_u32(&mbar);
    const float* __restrict__ src = I + (size_t)bid * RFLOATS;

    // --- TMA engine: first 16KB half into SMEM (single thread) ---
    if (t == 0) {
        asm volatile("mbarrier.init.shared.b64 [%0], 1;" :: "r"(mb) : "memory");
        asm volatile("fence.mbarrier_init.release.cluster;" ::: "memory");
    }
    __syncthreads();
    if (t == 0) {
        asm volatile("mbarrier.arrive.expect_tx.shared.b64 _, [%0], %1;"
                     :: "r"(mb), "r"((uint32_t)HBYTES) : "memory");
        asm volatile("cp.async.bulk.shared::cluster.global.mbarrier::complete_tx::bytes "
                     "[%0], [%1], %2, [%3];"
                     :: "r"(smem_u32(buf)), "l"(src), "r"((uint32_t)HBYTES), "r"(mb)
                     : "memory");
    }

    // --- LSU engine: second 16KB half via LDG (overlaps the TMA in flight) ---
    const float4* __restrict__ g4 =
        reinterpret_cast<const float4*>(src + HALF);
    float4 a = g4[t];
    float4 b = g4[t + 256];
    float4 c = g4[t + 512];
    float4 d = g4[t + 768];
    float s = ((a.x + a.y) + (a.z + a.w))
            + ((b.x + b.y) + (b.z + b.w))
            + ((c.x + c.y) + (c.z + c.w))
            + ((d.x + d.y) + (d.z + d.w));

    // --- wait for the TMA half (phase 0), then sum it from SMEM ---
    {
        uint32_t done;
        asm volatile("{\n\t.reg .pred p;\n\t"
                     "mbarrier.try_wait.parity.acquire.cta.shared::cta.b64 p, [%1], 0;\n\t"
                     "selp.b32 %0, 1, 0, p;\n\t}"
                     : "=r"(done) : "r"(mb) : "memory");
        while (!done) {
            asm volatile("{\n\t.reg .pred p;\n\t"
                         "mbarrier.try_wait.parity.acquire.cta.shared::cta.b64 p, [%1], 0, 0x989680;\n\t"
                         "selp.b32 %0, 1, 0, p;\n\t}"
                         : "=r"(done) : "r"(mb) : "memory");
        }
    }

    const float4* __restrict__ b4 = reinterpret_cast<const float4*>(buf);
    #pragma unroll
    for (int i = 0; i < 4; i++) {
        float4 v = b4[t + i * THREADS];
        s += (v.x + v.y) + (v.z + v.w);
    }

    #pragma unroll
    for (int off = 16; off > 0; off >>= 1)
        s += __shfl_xor_sync(0xffffffffu, s, off);

    __shared__ float wsum[THREADS / 32];
    if ((t & 31) == 0) wsum[t >> 5] = s;
    __syncthreads();

    if (t == 0) {
        float tot = 0.0f;
        #pragma unroll
        for (int i = 0; i < THREADS / 32; i++) tot += wsum[i];
        g_partials[bid] = tot;   // fixed slot -> deterministic
        cudaTriggerProgrammaticLaunchCompletion();
    }
}

// Epilogue (PDL secondary): prefetch T/Q/P before gridDepSync, then consume
// 1536 partials. 768 threads = 48 teams x 16 lanes, 2 loads per lane.
__global__ __launch_bounds__(768)
void dncm_final_kernel(const float* __restrict__ T,
                       const float* __restrict__ P,
                       const float* __restrict__ Q,
                       float* __restrict__ out) {
    const int t  = threadIdx.x;        // 0..767
    const int ch = t >> 4;             // 0..47
    const int j  = t & 15;             // lane within team

    // ---- Prefetch phase (overlaps with primary tail) ----
    const int b = t >> 4;              // batch (valid for t < 256)
    const int k = t & 15;
    float4 t0, t1, t2, t3;
    float r[KDIM];
    float P0 = 0.f, P1 = 0.f, P2 = 0.f;
    if (t < 256) {
        const float4* __restrict__ Tv =
            reinterpret_cast<const float4*>(T + b * (KDIM * KDIM) + k * KDIM);
        t0 = Tv[0]; t1 = Tv[1]; t2 = Tv[2]; t3 = Tv[3];
        #pragma unroll
        for (int q = 0; q < KDIM; q++)
            r[q] = Q[q * 3 + 0] + Q[q * 3 + 1] + Q[q * 3 + 2];
        P0 = P[0 * KDIM + k];
        P1 = P[1 * KDIM + k];
        P2 = P[2 * KDIM + k];
    }

    cudaGridDependencySynchronize();

    // ---- Reduce partials: 16 lanes per channel, 2 loads each ----
    const float* __restrict__ p = g_partials + ch * PARTS;
    float s = p[j] + p[j + 16];
    #pragma unroll
    for (int off = 8; off > 0; off >>= 1)
        s += __shfl_xor_sync(0xffffffffu, s, off);

    __shared__ float S[NCH];
    if (j == 0) S[ch] = s;
    __syncthreads();

    if (t < 256) {
        // A[b,k] = sum_c S[b,c] * P[c,k]
        const float A = S[b * CHANS + 0] * P0
                      + S[b * CHANS + 1] * P1
                      + S[b * CHANS + 2] * P2;

        // d = T_b[k,:] . r
        float d = t0.x * r[0]  + t0.y * r[1]  + t0.z * r[2]  + t0.w * r[3]
                + t1.x * r[4]  + t1.y * r[5]  + t1.z * r[6]  + t1.w * r[7]
                + t2.x * r[8]  + t2.y * r[9]  + t2.z * r[10] + t2.w * r[11]
                + t3.x * r[12] + t3.y * r[13] + t3.z * r[14] + t3.w * r[15];

        float val = d * A;
        #pragma unroll
        for (int off = 8; off > 0; off >>= 1)
            val += __shfl_xor_sync(0xffffffffu, val, off);

        if (k == 0)
            out[b] = val * (1.0f / (float)(HW * CHANS));
    }
}

extern "C" void kernel_launch(void* const* d_in, const int* in_sizes, int n_in,
                              void* d_out, int out_size) {
    const float* I = (const float*)d_in[0];   // (16,3,512,512)
    const float* T = (const float*)d_in[1];   // (16,256)
    const float* P = (const float*)d_in[2];   // (3,16)
    const float* Q = (const float*)d_in[3];   // (16,3)
    float* out = (float*)d_out;               // (16,1)

    dncm_reduce_kernel<<<NBLOCKS, THREADS>>>(I);

    cudaLaunchConfig_t cfg = {};
    cfg.gridDim  = dim3(1, 1, 1);
    cfg.blockDim = dim3(768, 1, 1);
    cfg.dynamicSmemBytes = 0;
    cfg.stream = 0;
    cudaLaunchAttribute attr[1];
    attr[0].id = cudaLaunchAttributeProgrammaticStreamSerialization;
    attr[0].val.programmaticStreamSerializationAllowed = 1;
    cfg.attrs = attr;
    cfg.numAttrs = 1;
    cudaLaunchKernelEx(&cfg, dncm_final_kernel, T, P, Q, out);
}